// round 1
// baseline (speedup 1.0000x reference)
#include <cuda_runtime.h>
#include <math.h>

#define HIDDEN 1024
#define NHEADS 16
#define HDIM   64
#define BB     4
#define SSEQ   1024
#define MTOT   (BB*SSEQ)   // 4096

// ---------------- scratch (device globals: allocation-free) ----------------
__device__ float g_q   [MTOT*HIDDEN];
__device__ float g_k   [MTOT*HIDDEN];
__device__ float g_vg  [MTOT*HIDDEN];
__device__ float g_ctx [MTOT*HIDDEN];
__device__ float g_ctxg[MTOT*HIDDEN];

__device__ __forceinline__ float sigmoidf_(float x) {
    return 1.0f / (1.0f + __expf(-x));
}

// ---------------------------------------------------------------------------
// Generic NT SGEMM:  C[m,n] = epi( sum_k A[m,k]*B[n,k] + bias[n] )
// A's K range is split: k < K1 reads A1 (row stride K1), else A2 (stride K-K1).
// EPI 0: C = v
// EPI 1: C = v * sigmoid(E[m,n])          (V gating by membrane potential)
// EPI 2: C = E[m,n] * sigmoid(v)          (dendritic gate applied to context)
// Tiles: BM=128, BN=128, BK=16, 256 threads, 8x8 per thread.
// ---------------------------------------------------------------------------
template<int EPI>
__global__ __launch_bounds__(256) void gemm_nt(
    const float* __restrict__ A1, const float* __restrict__ A2, int K1, int K,
    const float* __restrict__ Bm, const float* __restrict__ bias,
    const float* __restrict__ E,
    float* __restrict__ C, int M, int N)
{
    __shared__ float As[16][132];
    __shared__ float Bs[16][132];

    const int tid = threadIdx.x;
    const int ty = tid >> 4;      // 0..15
    const int tx = tid & 15;      // 0..15
    const int m0 = blockIdx.y * 128;
    const int n0 = blockIdx.x * 128;

    float acc[8][8];
#pragma unroll
    for (int i = 0; i < 8; i++)
#pragma unroll
        for (int j = 0; j < 8; j++) acc[i][j] = 0.0f;

    const int nkt = K >> 4;
    const int lda2 = K - K1;

    for (int kt = 0; kt < nkt; ++kt) {
        const int k0 = kt << 4;
#pragma unroll
        for (int u = 0; u < 2; ++u) {
            const int idx = tid + u * 256;        // 0..511
            const int row = idx >> 2;             // 0..127
            const int q   = idx & 3;              // 0..3 (quad of 4 k's)
            const int kg  = k0 + q * 4;

            const float* srcA;
            if (kg < K1) srcA = A1 + (size_t)(m0 + row) * K1 + kg;
            else         srcA = A2 + (size_t)(m0 + row) * lda2 + (kg - K1);
            float4 va = *(const float4*)srcA;
            As[q*4+0][row] = va.x; As[q*4+1][row] = va.y;
            As[q*4+2][row] = va.z; As[q*4+3][row] = va.w;

            float4 vb = *(const float4*)(Bm + (size_t)(n0 + row) * K + kg);
            Bs[q*4+0][row] = vb.x; Bs[q*4+1][row] = vb.y;
            Bs[q*4+2][row] = vb.z; Bs[q*4+3][row] = vb.w;
        }
        __syncthreads();

#pragma unroll
        for (int kk = 0; kk < 16; ++kk) {
            float a[8], b[8];
            *(float4*)&a[0] = *(const float4*)&As[kk][ty*8];
            *(float4*)&a[4] = *(const float4*)&As[kk][ty*8+4];
            *(float4*)&b[0] = *(const float4*)&Bs[kk][tx*8];
            *(float4*)&b[4] = *(const float4*)&Bs[kk][tx*8+4];
#pragma unroll
            for (int i = 0; i < 8; i++)
#pragma unroll
                for (int j = 0; j < 8; j++)
                    acc[i][j] = fmaf(a[i], b[j], acc[i][j]);
        }
        __syncthreads();
    }

    // epilogue
    float bvals[8];
#pragma unroll
    for (int j = 0; j < 8; j++) bvals[j] = bias[n0 + tx*8 + j];

#pragma unroll
    for (int i = 0; i < 8; i++) {
        const int m = m0 + ty*8 + i;
        const size_t off = (size_t)m * N + n0 + tx*8;
        float v[8];
#pragma unroll
        for (int j = 0; j < 8; j++) {
            float val = acc[i][j] + bvals[j];
            if (EPI == 1) val = val * sigmoidf_(E[off + j]);
            if (EPI == 2) val = E[off + j] * sigmoidf_(val);
            v[j] = val;
        }
        *(float4*)&C[off]     = make_float4(v[0], v[1], v[2], v[3]);
        *(float4*)&C[off + 4] = make_float4(v[4], v[5], v[6], v[7]);
    }
}

// ---------------------------------------------------------------------------
// Fused flash-style attention.
// Per block: one (b, h, 64-row q tile). Iterates 16 key tiles of 64.
// score = (q.k)*scale * exp(-|ti-tj|/tau_h) * (1 + (sq.sk)*scale)
// online softmax, acc += P @ Vgated.
// smem tiles (dynamic): Qt,SQt,Kt,SKt transposed [d][row], Vn,[key][d], Pt [key][row]
// ---------------------------------------------------------------------------
#define TPAD 68
#define ATTN_SMEM (6 * 64 * TPAD * 4)

__global__ __launch_bounds__(256) void attn_kernel(
    const float* __restrict__ qg, const float* __restrict__ kg,
    const float* __restrict__ vg, const float* __restrict__ spk,
    const float* __restrict__ tau, float* __restrict__ ctx)
{
    extern __shared__ float smem[];
    float* Qt  = smem;
    float* SQt = Qt  + 64 * TPAD;
    float* Kt  = SQt + 64 * TPAD;
    float* SKt = Kt  + 64 * TPAD;
    float* Vn  = SKt + 64 * TPAD;
    float* Pt  = Vn  + 64 * TPAD;

    const int tid = threadIdx.x;
    const int ty = tid >> 4;   // 0..15 -> rows ty*4..ty*4+3
    const int tx = tid & 15;   // 0..15 -> cols tx*4..tx*4+3
    const int qt = blockIdx.x, h = blockIdx.y, b = blockIdx.z;
    const int q0 = qt * 64;
    const float inv_tau = 1.0f / tau[h];
    const float scale = 0.125f; // 1/sqrt(64)

    // load Q and spike-Q tiles (transposed: [d][row])
#pragma unroll
    for (int u = 0; u < 4; ++u) {
        const int idx = tid + u * 256;      // 0..1023
        const int row = idx >> 4;           // 0..63
        const int qd  = idx & 15;           // 0..15 quads
        const size_t gro = ((size_t)(b * SSEQ + q0 + row)) * HIDDEN + h * HDIM + qd * 4;
        float4 v = *(const float4*)(qg + gro);
        Qt[(qd*4+0)*TPAD + row] = v.x; Qt[(qd*4+1)*TPAD + row] = v.y;
        Qt[(qd*4+2)*TPAD + row] = v.z; Qt[(qd*4+3)*TPAD + row] = v.w;
        float4 w = *(const float4*)(spk + gro);
        SQt[(qd*4+0)*TPAD + row] = w.x; SQt[(qd*4+1)*TPAD + row] = w.y;
        SQt[(qd*4+2)*TPAD + row] = w.z; SQt[(qd*4+3)*TPAD + row] = w.w;
    }

    float mrow[4], lrow[4], acc[4][4];
#pragma unroll
    for (int i = 0; i < 4; i++) {
        mrow[i] = -1e30f; lrow[i] = 0.0f;
#pragma unroll
        for (int j = 0; j < 4; j++) acc[i][j] = 0.0f;
    }

    for (int kt = 0; kt < 16; ++kt) {
        const int k0 = kt * 64;
        // load K, spike-K (transposed) and gated V (natural)
#pragma unroll
        for (int u = 0; u < 4; ++u) {
            const int idx = tid + u * 256;
            const int row = idx >> 4;
            const int qd  = idx & 15;
            const size_t gro = ((size_t)(b * SSEQ + k0 + row)) * HIDDEN + h * HDIM + qd * 4;
            float4 kv = *(const float4*)(kg + gro);
            Kt[(qd*4+0)*TPAD + row] = kv.x; Kt[(qd*4+1)*TPAD + row] = kv.y;
            Kt[(qd*4+2)*TPAD + row] = kv.z; Kt[(qd*4+3)*TPAD + row] = kv.w;
            float4 sv = *(const float4*)(spk + gro);
            SKt[(qd*4+0)*TPAD + row] = sv.x; SKt[(qd*4+1)*TPAD + row] = sv.y;
            SKt[(qd*4+2)*TPAD + row] = sv.z; SKt[(qd*4+3)*TPAD + row] = sv.w;
            float4 vv = *(const float4*)(vg + gro);
            *(float4*)&Vn[row * TPAD + qd * 4] = vv;
        }
        __syncthreads();

        // phase 1: raw scores + spike correlation
        float s[4][4], sp[4][4];
#pragma unroll
        for (int i = 0; i < 4; i++)
#pragma unroll
            for (int j = 0; j < 4; j++) { s[i][j] = 0.0f; sp[i][j] = 0.0f; }

#pragma unroll 8
        for (int d = 0; d < 64; ++d) {
            float4 aq = *(const float4*)&Qt [d*TPAD + ty*4];
            float4 as = *(const float4*)&SQt[d*TPAD + ty*4];
            float4 bk = *(const float4*)&Kt [d*TPAD + tx*4];
            float4 bs = *(const float4*)&SKt[d*TPAD + tx*4];
            float aqa[4] = {aq.x, aq.y, aq.z, aq.w};
            float asa[4] = {as.x, as.y, as.z, as.w};
            float bka[4] = {bk.x, bk.y, bk.z, bk.w};
            float bsa[4] = {bs.x, bs.y, bs.z, bs.w};
#pragma unroll
            for (int i = 0; i < 4; i++)
#pragma unroll
                for (int j = 0; j < 4; j++) {
                    s [i][j] = fmaf(aqa[i], bka[j], s [i][j]);
                    sp[i][j] = fmaf(asa[i], bsa[j], sp[i][j]);
                }
        }

        // mask + online softmax (rows shared by 16 lanes of the same half-warp)
        float pnew[4][4];
#pragma unroll
        for (int i = 0; i < 4; i++) {
            const float ti = (float)(q0 + ty*4 + i);
            float rmax = -1e30f;
#pragma unroll
            for (int j = 0; j < 4; j++) {
                const float tj = (float)(k0 + tx*4 + j);
                float sc = s[i][j] * scale
                         * __expf(-fabsf(ti - tj) * inv_tau)
                         * (1.0f + sp[i][j] * scale);
                pnew[i][j] = sc;
                rmax = fmaxf(rmax, sc);
            }
#pragma unroll
            for (int o = 8; o >= 1; o >>= 1)
                rmax = fmaxf(rmax, __shfl_xor_sync(0xffffffffu, rmax, o));
            const float mnew = fmaxf(mrow[i], rmax);
            float rsum = 0.0f;
#pragma unroll
            for (int j = 0; j < 4; j++) {
                const float p = __expf(pnew[i][j] - mnew);
                pnew[i][j] = p;
                rsum += p;
            }
#pragma unroll
            for (int o = 8; o >= 1; o >>= 1)
                rsum += __shfl_xor_sync(0xffffffffu, rsum, o);
            const float corr = __expf(mrow[i] - mnew);
            lrow[i] = lrow[i] * corr + rsum;
#pragma unroll
            for (int j = 0; j < 4; j++) acc[i][j] *= corr;
            mrow[i] = mnew;
        }
        // store P transposed: Pt[key][row]
#pragma unroll
        for (int j = 0; j < 4; j++)
            *(float4*)&Pt[(tx*4 + j) * TPAD + ty*4] =
                make_float4(pnew[0][j], pnew[1][j], pnew[2][j], pnew[3][j]);
        __syncthreads();

        // phase 2: acc += P @ V
#pragma unroll 8
        for (int kk = 0; kk < 64; ++kk) {
            float4 a  = *(const float4*)&Pt[kk*TPAD + ty*4];
            float4 bv = *(const float4*)&Vn[kk*TPAD + tx*4];
            float aa[4] = {a.x, a.y, a.z, a.w};
            float ba[4] = {bv.x, bv.y, bv.z, bv.w};
#pragma unroll
            for (int i = 0; i < 4; i++)
#pragma unroll
                for (int j = 0; j < 4; j++)
                    acc[i][j] = fmaf(aa[i], ba[j], acc[i][j]);
        }
        __syncthreads();
    }

    // write context [b,s,HIDDEN]
#pragma unroll
    for (int i = 0; i < 4; i++) {
        const float inv_l = 1.0f / lrow[i];
        const size_t m = (size_t)(b * SSEQ + q0 + ty*4 + i);
        *(float4*)&ctx[m * HIDDEN + h * HDIM + tx*4] =
            make_float4(acc[i][0]*inv_l, acc[i][1]*inv_l,
                        acc[i][2]*inv_l, acc[i][3]*inv_l);
    }
}

// ---------------------------------------------------------------------------
extern "C" void kernel_launch(void* const* d_in, const int* in_sizes, int n_in,
                              void* d_out, int out_size)
{
    const float* x   = (const float*)d_in[0];
    const float* spk = (const float*)d_in[1];
    const float* mp  = (const float*)d_in[2];
    const float* Wq  = (const float*)d_in[3];
    const float* bq  = (const float*)d_in[4];
    const float* Wk  = (const float*)d_in[5];
    const float* bk  = (const float*)d_in[6];
    const float* Wv  = (const float*)d_in[7];
    const float* bv  = (const float*)d_in[8];
    const float* Wo  = (const float*)d_in[9];
    const float* bo  = (const float*)d_in[10];
    const float* tau = (const float*)d_in[11];
    const float* Wg  = (const float*)d_in[12];
    const float* bg  = (const float*)d_in[13];
    float* out = (float*)d_out;

    float *q, *k, *vgp, *ctx, *ctxg;
    cudaGetSymbolAddress((void**)&q,    g_q);
    cudaGetSymbolAddress((void**)&k,    g_k);
    cudaGetSymbolAddress((void**)&vgp,  g_vg);
    cudaGetSymbolAddress((void**)&ctx,  g_ctx);
    cudaGetSymbolAddress((void**)&ctxg, g_ctxg);

    cudaFuncSetAttribute(attn_kernel,
                         cudaFuncAttributeMaxDynamicSharedMemorySize, ATTN_SMEM);

    dim3 tb(256);
    dim3 gb(HIDDEN / 128, MTOT / 128);   // (8, 32)

    // q = x @ Wq^T + bq ; k likewise ; vg = (x @ Wv^T + bv) * sigmoid(mp)
    gemm_nt<0><<<gb, tb>>>(x, nullptr, HIDDEN, HIDDEN, Wq, bq, nullptr, q,    MTOT, HIDDEN);
    gemm_nt<0><<<gb, tb>>>(x, nullptr, HIDDEN, HIDDEN, Wk, bk, nullptr, k,    MTOT, HIDDEN);
    gemm_nt<1><<<gb, tb>>>(x, nullptr, HIDDEN, HIDDEN, Wv, bv, mp,      vgp,  MTOT, HIDDEN);

    // fused attention with decay mask + spike correlation + online softmax
    dim3 ga(SSEQ / 64, NHEADS, BB);      // (16,16,4)
    attn_kernel<<<ga, tb, ATTN_SMEM>>>(q, k, vgp, spk, tau, ctx);

    // ctxg = ctx * sigmoid([ctx, mp] @ Wg^T + bg)
    gemm_nt<2><<<gb, tb>>>(ctx, mp, HIDDEN, 2 * HIDDEN, Wg, bg, ctx, ctxg, MTOT, HIDDEN);

    // out = ctxg @ Wo^T + bo
    gemm_nt<0><<<gb, tb>>>(ctxg, nullptr, HIDDEN, HIDDEN, Wo, bo, nullptr, out, MTOT, HIDDEN);
}

// round 3
// speedup vs baseline: 1.3972x; 1.3972x over previous
#include <cuda_runtime.h>
#include <cuda_bf16.h>
#include <math.h>
#include <stdint.h>

#define HIDDEN 1024
#define NHEADS 16
#define HDIM   64
#define BB     4
#define SSEQ   1024
#define MTOT   (BB*SSEQ)   // 4096

// ---------------- scratch (device globals: allocation-free) ----------------
__device__ float g_q   [MTOT*HIDDEN];
__device__ float g_k   [MTOT*HIDDEN];
__device__ float g_vg  [MTOT*HIDDEN];
__device__ float g_ctx [MTOT*HIDDEN];
__device__ float g_ctxg[MTOT*HIDDEN];

__device__ __forceinline__ float sigmoidf_(float x) {
    return 1.0f / (1.0f + __expf(-x));
}

__device__ __forceinline__ uint32_t smem_to_u32(const void* p) {
    uint32_t a;
    asm("{ .reg .u64 t; cvta.to.shared.u64 t, %1; cvt.u32.u64 %0, t; }"
        : "=r"(a) : "l"(p));
    return a;
}

// ---------------- mma.sync helpers (legacy tensor path, compute_103-safe) ---
__device__ __forceinline__ void ldsm_x4(uint32_t (&r)[4], uint32_t addr) {
    asm volatile("ldmatrix.sync.aligned.m8n8.x4.shared.b16 {%0,%1,%2,%3}, [%4];"
        : "=r"(r[0]), "=r"(r[1]), "=r"(r[2]), "=r"(r[3]) : "r"(addr));
}
__device__ __forceinline__ void mma_bf16(float (&d)[4], const uint32_t (&a)[4],
                                         const uint32_t* b) {
    asm volatile("mma.sync.aligned.m16n8k16.row.col.f32.bf16.bf16.f32 "
        "{%0,%1,%2,%3}, {%4,%5,%6,%7}, {%8,%9}, {%0,%1,%2,%3};"
        : "+f"(d[0]), "+f"(d[1]), "+f"(d[2]), "+f"(d[3])
        : "r"(a[0]), "r"(a[1]), "r"(a[2]), "r"(a[3]), "r"(b[0]), "r"(b[1]));
}

// split fp32 -> bf16 hi + bf16 lo (residual exact in fp32)
__device__ __forceinline__ void split2pack(float x, float y, uint32_t& hi, uint32_t& lo) {
    __nv_bfloat16 hx = __float2bfloat16_rn(x);
    __nv_bfloat16 hy = __float2bfloat16_rn(y);
    __nv_bfloat16 lx = __float2bfloat16_rn(x - __bfloat162float(hx));
    __nv_bfloat16 ly = __float2bfloat16_rn(y - __bfloat162float(hy));
    hi = (uint32_t)__bfloat16_as_ushort(hx) | ((uint32_t)__bfloat16_as_ushort(hy) << 16);
    lo = (uint32_t)__bfloat16_as_ushort(lx) | ((uint32_t)__bfloat16_as_ushort(ly) << 16);
}

// ---------------------------------------------------------------------------
// Split-bf16 tensor-core NT GEMM: C[m,n] = epi(sum_k A[m,k]*B[n,k] + bias[n])
// A K-range split: k<K1 reads A1 (stride K1), else A2 (stride K-K1).
// EPI 0: C=v   EPI 1: C=v*sigmoid(E)   EPI 2: C=E*sigmoid(v)
// 128x128 CTA tile, K-chunk 32. 8 warps, each 32(m)x64(n) = 2x8 m16n8k16 tiles.
// smem rows padded to 40 bf16 (80B) -> conflict-free ldmatrix.
// Double-buffered smem + global->reg prefetch.
// ---------------------------------------------------------------------------
#define BKP        40
#define TERM_BYTES (128*BKP*2)        // 10240
#define BUF_BYTES  (4*TERM_BYTES)     // 40960: Ah, Al, Bh, Bl
#define GEMM_SMEM  (2*BUF_BYTES)      // 81920

template<int EPI>
__global__ __launch_bounds__(256) void gemm_mma(
    const float* __restrict__ A1, const float* __restrict__ A2, int K1, int K,
    const float* __restrict__ Bm, const float* __restrict__ bias,
    const float* __restrict__ E,
    float* __restrict__ C, int M, int N)
{
    extern __shared__ __align__(128) char smem[];
    const uint32_t sbase = smem_to_u32(smem);
    const int tid = threadIdx.x, wid = tid >> 5, lane = tid & 31;
    const int m0 = blockIdx.y * 128, n0 = blockIdx.x * 128;
    const int NCH = K >> 5, lda2 = K - K1;

    const int wm = (wid >> 1) * 32;   // warp m offset in tile
    const int wn = (wid & 1) * 64;    // warp n offset in tile

    float acc[2][8][4];
#pragma unroll
    for (int mt = 0; mt < 2; mt++)
#pragma unroll
        for (int nt = 0; nt < 8; nt++)
#pragma unroll
            for (int j = 0; j < 4; j++) acc[mt][nt][j] = 0.0f;

    // global-load coords (per thread): 4 rows, fixed k-quad
    const int lrow = tid >> 3;          // 0..31
    const int lq4  = (tid & 7) * 4;     // k offset in chunk (floats)

    float4 ra[4], rb[4];

    auto load_chunk = [&](int c) {
        const int k0 = c * 32;
        const float* Ap; int lda, koff;
        if (k0 < K1) { Ap = A1; lda = K1;  koff = k0; }
        else         { Ap = A2; lda = lda2; koff = k0 - K1; }
#pragma unroll
        for (int u = 0; u < 4; ++u) {
            const int r = lrow + u * 32;
            ra[u] = *(const float4*)(Ap + (size_t)(m0 + r) * lda + koff + lq4);
            rb[u] = *(const float4*)(Bm + (size_t)(n0 + r) * K + k0 + lq4);
        }
    };
    auto store_chunk = [&](int buf) {
        char* base = smem + buf * BUF_BYTES;
#pragma unroll
        for (int u = 0; u < 4; ++u) {
            const int r = lrow + u * 32;
            const uint32_t off = (uint32_t)(r * (BKP * 2) + (tid & 7) * 8);
            uint2 hi, lo;
            split2pack(ra[u].x, ra[u].y, hi.x, lo.x);
            split2pack(ra[u].z, ra[u].w, hi.y, lo.y);
            *(uint2*)(base + off)              = hi;
            *(uint2*)(base + TERM_BYTES + off) = lo;
            split2pack(rb[u].x, rb[u].y, hi.x, lo.x);
            split2pack(rb[u].z, rb[u].w, hi.y, lo.y);
            *(uint2*)(base + 2 * TERM_BYTES + off) = hi;
            *(uint2*)(base + 3 * TERM_BYTES + off) = lo;
        }
    };

    // ldmatrix per-lane offsets (within a term region), in bytes
    //  A x4: m = wm + mt*16 + (lane&15), k = ks*16 + (lane>>4)*8
    const uint32_t a_lane_off = (uint32_t)((lane & 15) * (BKP * 2) + (lane >> 4) * 16);
    //  B x4 over 2 n-tiles: n = wn + np*16 + (lane&7) + ((lane>>4)<<3), k = ks*16 + ((lane>>3)&1)*8
    const uint32_t b_lane_off = (uint32_t)(((lane & 7) + ((lane >> 4) << 3)) * (BKP * 2)
                                           + ((lane >> 3) & 1) * 16);

    auto compute_chunk = [&](int buf) {
        const uint32_t b = sbase + (uint32_t)buf * BUF_BYTES;
#pragma unroll
        for (int ks = 0; ks < 2; ++ks) {
            const uint32_t koffb = (uint32_t)(ks * 32);  // 16 bf16 = 32 bytes
            uint32_t ah[2][4], al[2][4];
#pragma unroll
            for (int mt = 0; mt < 2; ++mt) {
                const uint32_t off = (uint32_t)((wm + mt * 16) * (BKP * 2)) + a_lane_off + koffb;
                ldsm_x4(ah[mt], b + off);
                ldsm_x4(al[mt], b + TERM_BYTES + off);
            }
            uint32_t bh[8][2], bl[8][2];
#pragma unroll
            for (int np = 0; np < 4; ++np) {
                const uint32_t off = (uint32_t)((wn + np * 16) * (BKP * 2)) + b_lane_off + koffb;
                uint32_t r4[4];
                ldsm_x4(r4, b + 2 * TERM_BYTES + off);
                bh[np*2][0] = r4[0]; bh[np*2][1] = r4[1];
                bh[np*2+1][0] = r4[2]; bh[np*2+1][1] = r4[3];
                ldsm_x4(r4, b + 3 * TERM_BYTES + off);
                bl[np*2][0] = r4[0]; bl[np*2][1] = r4[1];
                bl[np*2+1][0] = r4[2]; bl[np*2+1][1] = r4[3];
            }
#pragma unroll
            for (int mt = 0; mt < 2; ++mt)
#pragma unroll
                for (int nt = 0; nt < 8; ++nt) {
                    mma_bf16(acc[mt][nt], ah[mt], bh[nt]);
                    mma_bf16(acc[mt][nt], ah[mt], bl[nt]);
                    mma_bf16(acc[mt][nt], al[mt], bh[nt]);
                }
        }
    };

    // pipeline: prefetch chunk c+1 into regs while computing chunk c from smem
    load_chunk(0);
    store_chunk(0);
    __syncthreads();
    for (int c = 0; c < NCH; ++c) {
        if (c + 1 < NCH) load_chunk(c + 1);
        compute_chunk(c & 1);
        __syncthreads();
        if (c + 1 < NCH) {
            store_chunk((c + 1) & 1);
            __syncthreads();
        }
    }

    // epilogue: fragment layout c0,c1 -> (m, n),(m, n+1); c2,c3 -> (m+8, ...)
#pragma unroll
    for (int mt = 0; mt < 2; ++mt) {
        const int m = m0 + wm + mt * 16 + (lane >> 2);
#pragma unroll
        for (int nt = 0; nt < 8; ++nt) {
            const int n = n0 + wn + nt * 8 + (lane & 3) * 2;
            const float2 bv = *(const float2*)(bias + n);
            {
                const size_t off = (size_t)m * N + n;
                float v0 = acc[mt][nt][0] + bv.x;
                float v1 = acc[mt][nt][1] + bv.y;
                if (EPI == 1) {
                    float2 e = *(const float2*)(E + off);
                    v0 *= sigmoidf_(e.x); v1 *= sigmoidf_(e.y);
                }
                if (EPI == 2) {
                    float2 e = *(const float2*)(E + off);
                    v0 = e.x * sigmoidf_(v0); v1 = e.y * sigmoidf_(v1);
                }
                *(float2*)(C + off) = make_float2(v0, v1);
            }
            {
                const size_t off = (size_t)(m + 8) * N + n;
                float v0 = acc[mt][nt][2] + bv.x;
                float v1 = acc[mt][nt][3] + bv.y;
                if (EPI == 1) {
                    float2 e = *(const float2*)(E + off);
                    v0 *= sigmoidf_(e.x); v1 *= sigmoidf_(e.y);
                }
                if (EPI == 2) {
                    float2 e = *(const float2*)(E + off);
                    v0 = e.x * sigmoidf_(v0); v1 = e.y * sigmoidf_(v1);
                }
                *(float2*)(C + off) = make_float2(v0, v1);
            }
        }
    }
}

// ---------------------------------------------------------------------------
// Fused flash-style attention (round-1 version, unchanged).
// ---------------------------------------------------------------------------
#define TPAD 68
#define ATTN_SMEM (6 * 64 * TPAD * 4)

__global__ __launch_bounds__(256) void attn_kernel(
    const float* __restrict__ qg, const float* __restrict__ kg,
    const float* __restrict__ vg, const float* __restrict__ spk,
    const float* __restrict__ tau, float* __restrict__ ctx)
{
    extern __shared__ float smemf[];
    float* Qt  = smemf;
    float* SQt = Qt  + 64 * TPAD;
    float* Kt  = SQt + 64 * TPAD;
    float* SKt = Kt  + 64 * TPAD;
    float* Vn  = SKt + 64 * TPAD;
    float* Pt  = Vn  + 64 * TPAD;

    const int tid = threadIdx.x;
    const int ty = tid >> 4;
    const int tx = tid & 15;
    const int qt = blockIdx.x, h = blockIdx.y, b = blockIdx.z;
    const int q0 = qt * 64;
    const float inv_tau = 1.0f / tau[h];
    const float scale = 0.125f;

#pragma unroll
    for (int u = 0; u < 4; ++u) {
        const int idx = tid + u * 256;
        const int row = idx >> 4;
        const int qd  = idx & 15;
        const size_t gro = ((size_t)(b * SSEQ + q0 + row)) * HIDDEN + h * HDIM + qd * 4;
        float4 v = *(const float4*)(qg + gro);
        Qt[(qd*4+0)*TPAD + row] = v.x; Qt[(qd*4+1)*TPAD + row] = v.y;
        Qt[(qd*4+2)*TPAD + row] = v.z; Qt[(qd*4+3)*TPAD + row] = v.w;
        float4 w = *(const float4*)(spk + gro);
        SQt[(qd*4+0)*TPAD + row] = w.x; SQt[(qd*4+1)*TPAD + row] = w.y;
        SQt[(qd*4+2)*TPAD + row] = w.z; SQt[(qd*4+3)*TPAD + row] = w.w;
    }

    float mrow[4], lrow[4], acc[4][4];
#pragma unroll
    for (int i = 0; i < 4; i++) {
        mrow[i] = -1e30f; lrow[i] = 0.0f;
#pragma unroll
        for (int j = 0; j < 4; j++) acc[i][j] = 0.0f;
    }

    for (int kt = 0; kt < 16; ++kt) {
        const int k0 = kt * 64;
#pragma unroll
        for (int u = 0; u < 4; ++u) {
            const int idx = tid + u * 256;
            const int row = idx >> 4;
            const int qd  = idx & 15;
            const size_t gro = ((size_t)(b * SSEQ + k0 + row)) * HIDDEN + h * HDIM + qd * 4;
            float4 kv = *(const float4*)(kg + gro);
            Kt[(qd*4+0)*TPAD + row] = kv.x; Kt[(qd*4+1)*TPAD + row] = kv.y;
            Kt[(qd*4+2)*TPAD + row] = kv.z; Kt[(qd*4+3)*TPAD + row] = kv.w;
            float4 sv = *(const float4*)(spk + gro);
            SKt[(qd*4+0)*TPAD + row] = sv.x; SKt[(qd*4+1)*TPAD + row] = sv.y;
            SKt[(qd*4+2)*TPAD + row] = sv.z; SKt[(qd*4+3)*TPAD + row] = sv.w;
            float4 vv = *(const float4*)(vg + gro);
            *(float4*)&Vn[row * TPAD + qd * 4] = vv;
        }
        __syncthreads();

        float s[4][4], sp[4][4];
#pragma unroll
        for (int i = 0; i < 4; i++)
#pragma unroll
            for (int j = 0; j < 4; j++) { s[i][j] = 0.0f; sp[i][j] = 0.0f; }

#pragma unroll 8
        for (int d = 0; d < 64; ++d) {
            float4 aq = *(const float4*)&Qt [d*TPAD + ty*4];
            float4 as = *(const float4*)&SQt[d*TPAD + ty*4];
            float4 bk = *(const float4*)&Kt [d*TPAD + tx*4];
            float4 bs = *(const float4*)&SKt[d*TPAD + tx*4];
            float aqa[4] = {aq.x, aq.y, aq.z, aq.w};
            float asa[4] = {as.x, as.y, as.z, as.w};
            float bka[4] = {bk.x, bk.y, bk.z, bk.w};
            float bsa[4] = {bs.x, bs.y, bs.z, bs.w};
#pragma unroll
            for (int i = 0; i < 4; i++)
#pragma unroll
                for (int j = 0; j < 4; j++) {
                    s [i][j] = fmaf(aqa[i], bka[j], s [i][j]);
                    sp[i][j] = fmaf(asa[i], bsa[j], sp[i][j]);
                }
        }

        float pnew[4][4];
#pragma unroll
        for (int i = 0; i < 4; i++) {
            const float ti = (float)(q0 + ty*4 + i);
            float rmax = -1e30f;
#pragma unroll
            for (int j = 0; j < 4; j++) {
                const float tj = (float)(k0 + tx*4 + j);
                float sc = s[i][j] * scale
                         * __expf(-fabsf(ti - tj) * inv_tau)
                         * (1.0f + sp[i][j] * scale);
                pnew[i][j] = sc;
                rmax = fmaxf(rmax, sc);
            }
#pragma unroll
            for (int o = 8; o >= 1; o >>= 1)
                rmax = fmaxf(rmax, __shfl_xor_sync(0xffffffffu, rmax, o));
            const float mnew = fmaxf(mrow[i], rmax);
            float rsum = 0.0f;
#pragma unroll
            for (int j = 0; j < 4; j++) {
                const float p = __expf(pnew[i][j] - mnew);
                pnew[i][j] = p;
                rsum += p;
            }
#pragma unroll
            for (int o = 8; o >= 1; o >>= 1)
                rsum += __shfl_xor_sync(0xffffffffu, rsum, o);
            const float corr = __expf(mrow[i] - mnew);
            lrow[i] = lrow[i] * corr + rsum;
#pragma unroll
            for (int j = 0; j < 4; j++) acc[i][j] *= corr;
            mrow[i] = mnew;
        }
#pragma unroll
        for (int j = 0; j < 4; j++)
            *(float4*)&Pt[(tx*4 + j) * TPAD + ty*4] =
                make_float4(pnew[0][j], pnew[1][j], pnew[2][j], pnew[3][j]);
        __syncthreads();

#pragma unroll 8
        for (int kk = 0; kk < 64; ++kk) {
            float4 a  = *(const float4*)&Pt[kk*TPAD + ty*4];
            float4 bv = *(const float4*)&Vn[kk*TPAD + tx*4];
            float aa[4] = {a.x, a.y, a.z, a.w};
            float ba[4] = {bv.x, bv.y, bv.z, bv.w};
#pragma unroll
            for (int i = 0; i < 4; i++)
#pragma unroll
                for (int j = 0; j < 4; j++)
                    acc[i][j] = fmaf(aa[i], ba[j], acc[i][j]);
        }
        __syncthreads();
    }

#pragma unroll
    for (int i = 0; i < 4; i++) {
        const float inv_l = 1.0f / lrow[i];
        const size_t m = (size_t)(b * SSEQ + q0 + ty*4 + i);
        *(float4*)&ctx[m * HIDDEN + h * HDIM + tx*4] =
            make_float4(acc[i][0]*inv_l, acc[i][1]*inv_l,
                        acc[i][2]*inv_l, acc[i][3]*inv_l);
    }
}

// ---------------------------------------------------------------------------
extern "C" void kernel_launch(void* const* d_in, const int* in_sizes, int n_in,
                              void* d_out, int out_size)
{
    const float* x   = (const float*)d_in[0];
    const float* spk = (const float*)d_in[1];
    const float* mp  = (const float*)d_in[2];
    const float* Wq  = (const float*)d_in[3];
    const float* bq  = (const float*)d_in[4];
    const float* Wk  = (const float*)d_in[5];
    const float* bk  = (const float*)d_in[6];
    const float* Wv  = (const float*)d_in[7];
    const float* bv  = (const float*)d_in[8];
    const float* Wo  = (const float*)d_in[9];
    const float* bo  = (const float*)d_in[10];
    const float* tau = (const float*)d_in[11];
    const float* Wg  = (const float*)d_in[12];
    const float* bg  = (const float*)d_in[13];
    float* out = (float*)d_out;

    float *q, *k, *vgp, *ctx, *ctxg;
    cudaGetSymbolAddress((void**)&q,    g_q);
    cudaGetSymbolAddress((void**)&k,    g_k);
    cudaGetSymbolAddress((void**)&vgp,  g_vg);
    cudaGetSymbolAddress((void**)&ctx,  g_ctx);
    cudaGetSymbolAddress((void**)&ctxg, g_ctxg);

    cudaFuncSetAttribute(gemm_mma<0>, cudaFuncAttributeMaxDynamicSharedMemorySize, GEMM_SMEM);
    cudaFuncSetAttribute(gemm_mma<1>, cudaFuncAttributeMaxDynamicSharedMemorySize, GEMM_SMEM);
    cudaFuncSetAttribute(gemm_mma<2>, cudaFuncAttributeMaxDynamicSharedMemorySize, GEMM_SMEM);
    cudaFuncSetAttribute(attn_kernel, cudaFuncAttributeMaxDynamicSharedMemorySize, ATTN_SMEM);

    dim3 tb(256);
    dim3 gb(HIDDEN / 128, MTOT / 128);   // (8, 32)

    gemm_mma<0><<<gb, tb, GEMM_SMEM>>>(x, nullptr, HIDDEN, HIDDEN, Wq, bq, nullptr, q,   MTOT, HIDDEN);
    gemm_mma<0><<<gb, tb, GEMM_SMEM>>>(x, nullptr, HIDDEN, HIDDEN, Wk, bk, nullptr, k,   MTOT, HIDDEN);
    gemm_mma<1><<<gb, tb, GEMM_SMEM>>>(x, nullptr, HIDDEN, HIDDEN, Wv, bv, mp,      vgp, MTOT, HIDDEN);

    dim3 ga(SSEQ / 64, NHEADS, BB);      // (16,16,4)
    attn_kernel<<<ga, tb, ATTN_SMEM>>>(q, k, vgp, spk, tau, ctx);

    gemm_mma<2><<<gb, tb, GEMM_SMEM>>>(ctx, mp, HIDDEN, 2 * HIDDEN, Wg, bg, ctx, ctxg, MTOT, HIDDEN);
    gemm_mma<0><<<gb, tb, GEMM_SMEM>>>(ctxg, nullptr, HIDDEN, HIDDEN, Wo, bo, nullptr, out, MTOT, HIDDEN);
}

// round 4
// speedup vs baseline: 2.0253x; 1.4496x over previous
#include <cuda_runtime.h>
#include <cuda_bf16.h>
#include <math.h>
#include <stdint.h>

#define HIDDEN 1024
#define NHEADS 16
#define HDIM   64
#define BB     4
#define SSEQ   1024
#define MTOT   (BB*SSEQ)   // 4096

// ---------------- scratch (device globals: allocation-free) ----------------
__device__ float g_q   [MTOT*HIDDEN];
__device__ float g_k   [MTOT*HIDDEN];
__device__ float g_vg  [MTOT*HIDDEN];
__device__ float g_ctx [MTOT*HIDDEN];
__device__ float g_ctxg[MTOT*HIDDEN];

__device__ __forceinline__ float sigmoidf_(float x) {
    return 1.0f / (1.0f + __expf(-x));
}

__device__ __forceinline__ uint32_t smem_to_u32(const void* p) {
    uint32_t a;
    asm("{ .reg .u64 t; cvta.to.shared.u64 t, %1; cvt.u32.u64 %0, t; }"
        : "=r"(a) : "l"(p));
    return a;
}

// ---------------- mma.sync helpers (legacy tensor path, compute_103-safe) ---
__device__ __forceinline__ void ldsm_x4(uint32_t (&r)[4], uint32_t addr) {
    asm volatile("ldmatrix.sync.aligned.m8n8.x4.shared.b16 {%0,%1,%2,%3}, [%4];"
        : "=r"(r[0]), "=r"(r[1]), "=r"(r[2]), "=r"(r[3]) : "r"(addr));
}
__device__ __forceinline__ void ldsm_x4_trans(uint32_t (&r)[4], uint32_t addr) {
    asm volatile("ldmatrix.sync.aligned.m8n8.x4.trans.shared.b16 {%0,%1,%2,%3}, [%4];"
        : "=r"(r[0]), "=r"(r[1]), "=r"(r[2]), "=r"(r[3]) : "r"(addr));
}
__device__ __forceinline__ void mma_bf16(float (&d)[4], const uint32_t (&a)[4],
                                         const uint32_t* b) {
    asm volatile("mma.sync.aligned.m16n8k16.row.col.f32.bf16.bf16.f32 "
        "{%0,%1,%2,%3}, {%4,%5,%6,%7}, {%8,%9}, {%0,%1,%2,%3};"
        : "+f"(d[0]), "+f"(d[1]), "+f"(d[2]), "+f"(d[3])
        : "r"(a[0]), "r"(a[1]), "r"(a[2]), "r"(a[3]), "r"(b[0]), "r"(b[1]));
}

// split fp32 -> bf16 hi + bf16 lo (residual), packed x2
__device__ __forceinline__ void split2pack(float x, float y, uint32_t& hi, uint32_t& lo) {
    __nv_bfloat16 hx = __float2bfloat16_rn(x);
    __nv_bfloat16 hy = __float2bfloat16_rn(y);
    __nv_bfloat16 lx = __float2bfloat16_rn(x - __bfloat162float(hx));
    __nv_bfloat16 ly = __float2bfloat16_rn(y - __bfloat162float(hy));
    hi = (uint32_t)__bfloat16_as_ushort(hx) | ((uint32_t)__bfloat16_as_ushort(hy) << 16);
    lo = (uint32_t)__bfloat16_as_ushort(lx) | ((uint32_t)__bfloat16_as_ushort(ly) << 16);
}

// ---------------------------------------------------------------------------
// Split-bf16 tensor-core NT GEMM (unchanged from round 3 — passing).
// ---------------------------------------------------------------------------
#define BKP        40
#define TERM_BYTES (128*BKP*2)        // 10240
#define BUF_BYTES  (4*TERM_BYTES)     // 40960
#define GEMM_SMEM  (2*BUF_BYTES)      // 81920

template<int EPI>
__global__ __launch_bounds__(256) void gemm_mma(
    const float* __restrict__ A1, const float* __restrict__ A2, int K1, int K,
    const float* __restrict__ Bm, const float* __restrict__ bias,
    const float* __restrict__ E,
    float* __restrict__ C, int M, int N)
{
    extern __shared__ __align__(128) char smem[];
    const uint32_t sbase = smem_to_u32(smem);
    const int tid = threadIdx.x, wid = tid >> 5, lane = tid & 31;
    const int m0 = blockIdx.y * 128, n0 = blockIdx.x * 128;
    const int NCH = K >> 5, lda2 = K - K1;

    const int wm = (wid >> 1) * 32;
    const int wn = (wid & 1) * 64;

    float acc[2][8][4];
#pragma unroll
    for (int mt = 0; mt < 2; mt++)
#pragma unroll
        for (int nt = 0; nt < 8; nt++)
#pragma unroll
            for (int j = 0; j < 4; j++) acc[mt][nt][j] = 0.0f;

    const int lrow = tid >> 3;
    const int lq4  = (tid & 7) * 4;

    float4 ra[4], rb[4];

    auto load_chunk = [&](int c) {
        const int k0 = c * 32;
        const float* Ap; int lda, koff;
        if (k0 < K1) { Ap = A1; lda = K1;  koff = k0; }
        else         { Ap = A2; lda = lda2; koff = k0 - K1; }
#pragma unroll
        for (int u = 0; u < 4; ++u) {
            const int r = lrow + u * 32;
            ra[u] = *(const float4*)(Ap + (size_t)(m0 + r) * lda + koff + lq4);
            rb[u] = *(const float4*)(Bm + (size_t)(n0 + r) * K + k0 + lq4);
        }
    };
    auto store_chunk = [&](int buf) {
        char* base = smem + buf * BUF_BYTES;
#pragma unroll
        for (int u = 0; u < 4; ++u) {
            const int r = lrow + u * 32;
            const uint32_t off = (uint32_t)(r * (BKP * 2) + (tid & 7) * 8);
            uint2 hi, lo;
            split2pack(ra[u].x, ra[u].y, hi.x, lo.x);
            split2pack(ra[u].z, ra[u].w, hi.y, lo.y);
            *(uint2*)(base + off)              = hi;
            *(uint2*)(base + TERM_BYTES + off) = lo;
            split2pack(rb[u].x, rb[u].y, hi.x, lo.x);
            split2pack(rb[u].z, rb[u].w, hi.y, lo.y);
            *(uint2*)(base + 2 * TERM_BYTES + off) = hi;
            *(uint2*)(base + 3 * TERM_BYTES + off) = lo;
        }
    };

    const uint32_t a_lane_off = (uint32_t)((lane & 15) * (BKP * 2) + (lane >> 4) * 16);
    const uint32_t b_lane_off = (uint32_t)(((lane & 7) + ((lane >> 4) << 3)) * (BKP * 2)
                                           + ((lane >> 3) & 1) * 16);

    auto compute_chunk = [&](int buf) {
        const uint32_t b = sbase + (uint32_t)buf * BUF_BYTES;
#pragma unroll
        for (int ks = 0; ks < 2; ++ks) {
            const uint32_t koffb = (uint32_t)(ks * 32);
            uint32_t ah[2][4], al[2][4];
#pragma unroll
            for (int mt = 0; mt < 2; ++mt) {
                const uint32_t off = (uint32_t)((wm + mt * 16) * (BKP * 2)) + a_lane_off + koffb;
                ldsm_x4(ah[mt], b + off);
                ldsm_x4(al[mt], b + TERM_BYTES + off);
            }
            uint32_t bh[8][2], bl[8][2];
#pragma unroll
            for (int np = 0; np < 4; ++np) {
                const uint32_t off = (uint32_t)((wn + np * 16) * (BKP * 2)) + b_lane_off + koffb;
                uint32_t r4[4];
                ldsm_x4(r4, b + 2 * TERM_BYTES + off);
                bh[np*2][0] = r4[0]; bh[np*2][1] = r4[1];
                bh[np*2+1][0] = r4[2]; bh[np*2+1][1] = r4[3];
                ldsm_x4(r4, b + 3 * TERM_BYTES + off);
                bl[np*2][0] = r4[0]; bl[np*2][1] = r4[1];
                bl[np*2+1][0] = r4[2]; bl[np*2+1][1] = r4[3];
            }
#pragma unroll
            for (int mt = 0; mt < 2; ++mt)
#pragma unroll
                for (int nt = 0; nt < 8; ++nt) {
                    mma_bf16(acc[mt][nt], ah[mt], bh[nt]);
                    mma_bf16(acc[mt][nt], ah[mt], bl[nt]);
                    mma_bf16(acc[mt][nt], al[mt], bh[nt]);
                }
        }
    };

    load_chunk(0);
    store_chunk(0);
    __syncthreads();
    for (int c = 0; c < NCH; ++c) {
        if (c + 1 < NCH) load_chunk(c + 1);
        compute_chunk(c & 1);
        __syncthreads();
        if (c + 1 < NCH) {
            store_chunk((c + 1) & 1);
            __syncthreads();
        }
    }

#pragma unroll
    for (int mt = 0; mt < 2; ++mt) {
        const int m = m0 + wm + mt * 16 + (lane >> 2);
#pragma unroll
        for (int nt = 0; nt < 8; ++nt) {
            const int n = n0 + wn + nt * 8 + (lane & 3) * 2;
            const float2 bv = *(const float2*)(bias + n);
            {
                const size_t off = (size_t)m * N + n;
                float v0 = acc[mt][nt][0] + bv.x;
                float v1 = acc[mt][nt][1] + bv.y;
                if (EPI == 1) {
                    float2 e = *(const float2*)(E + off);
                    v0 *= sigmoidf_(e.x); v1 *= sigmoidf_(e.y);
                }
                if (EPI == 2) {
                    float2 e = *(const float2*)(E + off);
                    v0 = e.x * sigmoidf_(v0); v1 = e.y * sigmoidf_(v1);
                }
                *(float2*)(C + off) = make_float2(v0, v1);
            }
            {
                const size_t off = (size_t)(m + 8) * N + n;
                float v0 = acc[mt][nt][2] + bv.x;
                float v1 = acc[mt][nt][3] + bv.y;
                if (EPI == 1) {
                    float2 e = *(const float2*)(E + off);
                    v0 *= sigmoidf_(e.x); v1 *= sigmoidf_(e.y);
                }
                if (EPI == 2) {
                    float2 e = *(const float2*)(E + off);
                    v0 = e.x * sigmoidf_(v0); v1 = e.y * sigmoidf_(v1);
                }
                *(float2*)(C + off) = make_float2(v0, v1);
            }
        }
    }
}

// ---------------------------------------------------------------------------
// Tensor-core flash attention with split-bf16 mma.sync.
// Block: (b, h, 128-row q tile), 256 threads / 8 warps; warp w owns q rows
// q0+16w..+15. Loops over 16 K-tiles of 64 rows. Q/SQ live in registers as
// A fragments (scale folded in). K/SK/V in smem split hi/lo bf16.
// score = (q.k) * exp(-|dt|/tau) * (1 + sq.sk); online softmax; acc += P@V.
// ---------------------------------------------------------------------------
#define KROW   144                     // 72 bf16 per row (64 + 8 pad)
#define AT_KH  0
#define AT_KL  (64*KROW)               // 9216
#define AT_SKH (2*64*KROW)
#define AT_SKL (3*64*KROW)
#define AT_VH  (4*64*KROW)
#define AT_VL  (5*64*KROW)
#define ATTN_SMEM (6*64*KROW)          // 55296

__global__ __launch_bounds__(256, 1) void attn_mma(
    const float* __restrict__ qg, const float* __restrict__ kg,
    const float* __restrict__ vg, const float* __restrict__ spk,
    const float* __restrict__ tau, float* __restrict__ ctx)
{
    extern __shared__ __align__(128) char smem[];
    const uint32_t sb = smem_to_u32(smem);
    const int tid = threadIdx.x, wid = tid >> 5, lane = tid & 31;
    const int lane4 = lane & 3, laneq = lane >> 2;
    const int h = blockIdx.y, b = blockIdx.z;
    const int q0 = blockIdx.x * 128;
    const float inv_tau = 1.0f / tau[h];
    const float scale = 0.125f;

    // ---- Q / SQ register A-fragments (scale folded into both) ----
    uint32_t qh[4][4], ql[4][4], sqh[4][4], sql[4][4];
    const int ti0 = q0 + wid * 16 + laneq;
    const int ti1 = ti0 + 8;
    {
        const size_t r0b = (size_t)(b * SSEQ + ti0) * HIDDEN + h * HDIM;
        const size_t r1b = (size_t)(b * SSEQ + ti1) * HIDDEN + h * HDIM;
#pragma unroll
        for (int ks = 0; ks < 4; ++ks) {
            const int kc = ks * 16 + lane4 * 2;
            float2 v;
            v = *(const float2*)(qg + r0b + kc);
            split2pack(v.x * scale, v.y * scale, qh[ks][0], ql[ks][0]);
            v = *(const float2*)(qg + r1b + kc);
            split2pack(v.x * scale, v.y * scale, qh[ks][1], ql[ks][1]);
            v = *(const float2*)(qg + r0b + kc + 8);
            split2pack(v.x * scale, v.y * scale, qh[ks][2], ql[ks][2]);
            v = *(const float2*)(qg + r1b + kc + 8);
            split2pack(v.x * scale, v.y * scale, qh[ks][3], ql[ks][3]);
            v = *(const float2*)(spk + r0b + kc);
            split2pack(v.x * scale, v.y * scale, sqh[ks][0], sql[ks][0]);
            v = *(const float2*)(spk + r1b + kc);
            split2pack(v.x * scale, v.y * scale, sqh[ks][1], sql[ks][1]);
            v = *(const float2*)(spk + r0b + kc + 8);
            split2pack(v.x * scale, v.y * scale, sqh[ks][2], sql[ks][2]);
            v = *(const float2*)(spk + r1b + kc + 8);
            split2pack(v.x * scale, v.y * scale, sqh[ks][3], sql[ks][3]);
        }
    }

    float m0r = -1e30f, m1r = -1e30f, l0r = 0.0f, l1r = 0.0f;
    float o[8][4];
#pragma unroll
    for (int nt = 0; nt < 8; nt++)
#pragma unroll
        for (int j = 0; j < 4; j++) o[nt][j] = 0.0f;

    // ldmatrix lane offsets
    const uint32_t b_off = (uint32_t)(((lane & 7) + ((lane >> 4) << 3)) * KROW
                                      + ((lane >> 3) & 1) * 16);
    const uint32_t v_off = (uint32_t)(((lane & 7) + ((lane >> 3) & 1) * 8) * KROW
                                      + ((lane >> 4) & 1) * 16);

    const float ti0f = (float)ti0, ti1f = (float)ti1;

    for (int kt = 0; kt < 16; ++kt) {
        const int k0 = kt * 64;
        __syncthreads();
        // ---- fill smem: K, SK, V (split hi/lo) ----
#pragma unroll
        for (int u = 0; u < 4; ++u) {
            const int lin = tid + u * 256;
            const int row = lin >> 4, qd = lin & 15;
            const size_t g = ((size_t)(b * SSEQ + k0 + row)) * HIDDEN + h * HDIM + qd * 4;
            const uint32_t so = (uint32_t)(row * KROW + qd * 8);
            uint2 hi, lo;
            float4 t;
            t = *(const float4*)(kg + g);
            split2pack(t.x, t.y, hi.x, lo.x); split2pack(t.z, t.w, hi.y, lo.y);
            *(uint2*)(smem + AT_KH + so) = hi; *(uint2*)(smem + AT_KL + so) = lo;
            t = *(const float4*)(spk + g);
            split2pack(t.x, t.y, hi.x, lo.x); split2pack(t.z, t.w, hi.y, lo.y);
            *(uint2*)(smem + AT_SKH + so) = hi; *(uint2*)(smem + AT_SKL + so) = lo;
            t = *(const float4*)(vg + g);
            split2pack(t.x, t.y, hi.x, lo.x); split2pack(t.z, t.w, hi.y, lo.y);
            *(uint2*)(smem + AT_VH + so) = hi; *(uint2*)(smem + AT_VL + so) = lo;
        }
        __syncthreads();

        // ---- scores: s = (q.k), sp = (sq.sk), both pre-scaled ----
        float s[8][4], sp[8][4];
#pragma unroll
        for (int nt = 0; nt < 8; nt++)
#pragma unroll
            for (int j = 0; j < 4; j++) { s[nt][j] = 0.0f; sp[nt][j] = 0.0f; }

#pragma unroll
        for (int ks = 0; ks < 4; ++ks) {
            const uint32_t kb = (uint32_t)(ks * 32);
#pragma unroll
            for (int n8 = 0; n8 < 4; ++n8) {
                const uint32_t off = (uint32_t)(n8 * 16 * KROW) + b_off + kb;
                uint32_t rh[4], rl[4];
                ldsm_x4(rh, sb + AT_KH + off);
                ldsm_x4(rl, sb + AT_KL + off);
                mma_bf16(s[2*n8],   qh[ks], &rh[0]);
                mma_bf16(s[2*n8],   qh[ks], &rl[0]);
                mma_bf16(s[2*n8],   ql[ks], &rh[0]);
                mma_bf16(s[2*n8+1], qh[ks], &rh[2]);
                mma_bf16(s[2*n8+1], qh[ks], &rl[2]);
                mma_bf16(s[2*n8+1], ql[ks], &rh[2]);
                ldsm_x4(rh, sb + AT_SKH + off);
                ldsm_x4(rl, sb + AT_SKL + off);
                mma_bf16(sp[2*n8],   sqh[ks], &rh[0]);
                mma_bf16(sp[2*n8],   sqh[ks], &rl[0]);
                mma_bf16(sp[2*n8],   sql[ks], &rh[0]);
                mma_bf16(sp[2*n8+1], sqh[ks], &rh[2]);
                mma_bf16(sp[2*n8+1], sqh[ks], &rl[2]);
                mma_bf16(sp[2*n8+1], sql[ks], &rh[2]);
            }
        }

        // ---- mask + online softmax ----
        float rmax0 = -1e30f, rmax1 = -1e30f;
#pragma unroll
        for (int nt = 0; nt < 8; ++nt) {
            const float tjb = (float)(k0 + nt * 8 + lane4 * 2);
            const float e00 = __expf(-fabsf(ti0f - tjb) * inv_tau);
            const float e01 = __expf(-fabsf(ti0f - tjb - 1.0f) * inv_tau);
            const float e10 = __expf(-fabsf(ti1f - tjb) * inv_tau);
            const float e11 = __expf(-fabsf(ti1f - tjb - 1.0f) * inv_tau);
            s[nt][0] = s[nt][0] * e00 * (1.0f + sp[nt][0]);
            s[nt][1] = s[nt][1] * e01 * (1.0f + sp[nt][1]);
            s[nt][2] = s[nt][2] * e10 * (1.0f + sp[nt][2]);
            s[nt][3] = s[nt][3] * e11 * (1.0f + sp[nt][3]);
            rmax0 = fmaxf(rmax0, fmaxf(s[nt][0], s[nt][1]));
            rmax1 = fmaxf(rmax1, fmaxf(s[nt][2], s[nt][3]));
        }
        rmax0 = fmaxf(rmax0, __shfl_xor_sync(0xffffffffu, rmax0, 1));
        rmax0 = fmaxf(rmax0, __shfl_xor_sync(0xffffffffu, rmax0, 2));
        rmax1 = fmaxf(rmax1, __shfl_xor_sync(0xffffffffu, rmax1, 1));
        rmax1 = fmaxf(rmax1, __shfl_xor_sync(0xffffffffu, rmax1, 2));
        const float mn0 = fmaxf(m0r, rmax0), mn1 = fmaxf(m1r, rmax1);
        const float c0 = __expf(m0r - mn0), c1 = __expf(m1r - mn1);
        float ls0 = 0.0f, ls1 = 0.0f;
#pragma unroll
        for (int nt = 0; nt < 8; ++nt) {
            float p;
            p = __expf(s[nt][0] - mn0); s[nt][0] = p; ls0 += p;
            p = __expf(s[nt][1] - mn0); s[nt][1] = p; ls0 += p;
            p = __expf(s[nt][2] - mn1); s[nt][2] = p; ls1 += p;
            p = __expf(s[nt][3] - mn1); s[nt][3] = p; ls1 += p;
        }
        ls0 += __shfl_xor_sync(0xffffffffu, ls0, 1);
        ls0 += __shfl_xor_sync(0xffffffffu, ls0, 2);
        ls1 += __shfl_xor_sync(0xffffffffu, ls1, 1);
        ls1 += __shfl_xor_sync(0xffffffffu, ls1, 2);
        l0r = l0r * c0 + ls0;  m0r = mn0;
        l1r = l1r * c1 + ls1;  m1r = mn1;
#pragma unroll
        for (int nt = 0; nt < 8; ++nt) {
            o[nt][0] *= c0; o[nt][1] *= c0;
            o[nt][2] *= c1; o[nt][3] *= c1;
        }

        // ---- acc += P @ V (P frags repacked from score accumulators) ----
#pragma unroll
        for (int ks = 0; ks < 4; ++ks) {
            uint32_t ah[4], al[4];
            split2pack(s[2*ks][0],   s[2*ks][1],   ah[0], al[0]);
            split2pack(s[2*ks][2],   s[2*ks][3],   ah[1], al[1]);
            split2pack(s[2*ks+1][0], s[2*ks+1][1], ah[2], al[2]);
            split2pack(s[2*ks+1][2], s[2*ks+1][3], ah[3], al[3]);
            const uint32_t roff = (uint32_t)(ks * 16 * KROW) + v_off;
#pragma unroll
            for (int n8 = 0; n8 < 4; ++n8) {
                const uint32_t off = roff + (uint32_t)(n8 * 32);
                uint32_t vh[4], vl[4];
                ldsm_x4_trans(vh, sb + AT_VH + off);
                ldsm_x4_trans(vl, sb + AT_VL + off);
                mma_bf16(o[2*n8],   ah, &vh[0]);
                mma_bf16(o[2*n8],   ah, &vl[0]);
                mma_bf16(o[2*n8],   al, &vh[0]);
                mma_bf16(o[2*n8+1], ah, &vh[2]);
                mma_bf16(o[2*n8+1], ah, &vl[2]);
                mma_bf16(o[2*n8+1], al, &vh[2]);
            }
        }
    }

    // ---- write ctx ----
    const float inv0 = 1.0f / l0r, inv1 = 1.0f / l1r;
    const size_t r0b = (size_t)(b * SSEQ + ti0) * HIDDEN + h * HDIM;
    const size_t r1b = (size_t)(b * SSEQ + ti1) * HIDDEN + h * HDIM;
#pragma unroll
    for (int nt = 0; nt < 8; ++nt) {
        const int d = nt * 8 + lane4 * 2;
        *(float2*)(ctx + r0b + d) = make_float2(o[nt][0] * inv0, o[nt][1] * inv0);
        *(float2*)(ctx + r1b + d) = make_float2(o[nt][2] * inv1, o[nt][3] * inv1);
    }
}

// ---------------------------------------------------------------------------
extern "C" void kernel_launch(void* const* d_in, const int* in_sizes, int n_in,
                              void* d_out, int out_size)
{
    const float* x   = (const float*)d_in[0];
    const float* spk = (const float*)d_in[1];
    const float* mp  = (const float*)d_in[2];
    const float* Wq  = (const float*)d_in[3];
    const float* bq  = (const float*)d_in[4];
    const float* Wk  = (const float*)d_in[5];
    const float* bk  = (const float*)d_in[6];
    const float* Wv  = (const float*)d_in[7];
    const float* bv  = (const float*)d_in[8];
    const float* Wo  = (const float*)d_in[9];
    const float* bo  = (const float*)d_in[10];
    const float* tau = (const float*)d_in[11];
    const float* Wg  = (const float*)d_in[12];
    const float* bg  = (const float*)d_in[13];
    float* out = (float*)d_out;

    float *q, *k, *vgp, *ctx, *ctxg;
    cudaGetSymbolAddress((void**)&q,    g_q);
    cudaGetSymbolAddress((void**)&k,    g_k);
    cudaGetSymbolAddress((void**)&vgp,  g_vg);
    cudaGetSymbolAddress((void**)&ctx,  g_ctx);
    cudaGetSymbolAddress((void**)&ctxg, g_ctxg);

    cudaFuncSetAttribute(gemm_mma<0>, cudaFuncAttributeMaxDynamicSharedMemorySize, GEMM_SMEM);
    cudaFuncSetAttribute(gemm_mma<1>, cudaFuncAttributeMaxDynamicSharedMemorySize, GEMM_SMEM);
    cudaFuncSetAttribute(gemm_mma<2>, cudaFuncAttributeMaxDynamicSharedMemorySize, GEMM_SMEM);
    cudaFuncSetAttribute(attn_mma,    cudaFuncAttributeMaxDynamicSharedMemorySize, ATTN_SMEM);

    dim3 tb(256);
    dim3 gb(HIDDEN / 128, MTOT / 128);   // (8, 32)

    gemm_mma<0><<<gb, tb, GEMM_SMEM>>>(x, nullptr, HIDDEN, HIDDEN, Wq, bq, nullptr, q,   MTOT, HIDDEN);
    gemm_mma<0><<<gb, tb, GEMM_SMEM>>>(x, nullptr, HIDDEN, HIDDEN, Wk, bk, nullptr, k,   MTOT, HIDDEN);
    gemm_mma<1><<<gb, tb, GEMM_SMEM>>>(x, nullptr, HIDDEN, HIDDEN, Wv, bv, mp,      vgp, MTOT, HIDDEN);

    dim3 ga(SSEQ / 128, NHEADS, BB);     // (8,16,4)
    attn_mma<<<ga, tb, ATTN_SMEM>>>(q, k, vgp, spk, tau, ctx);

    gemm_mma<2><<<gb, tb, GEMM_SMEM>>>(ctx, mp, HIDDEN, 2 * HIDDEN, Wg, bg, ctx, ctxg, MTOT, HIDDEN);
    gemm_mma<0><<<gb, tb, GEMM_SMEM>>>(ctxg, nullptr, HIDDEN, HIDDEN, Wo, bo, nullptr, out, MTOT, HIDDEN);
}